// round 11
// baseline (speedup 1.0000x reference)
#include <cuda_runtime.h>
#include <math.h>
#include <stdint.h>

#define BQ    16
#define SEQ   512
#define NFch  32
#define ECH   128
#define HID   512
#define PRED  96
#define NFFT  64
#define HOPL  32
#define TOPM  32
#define WN    17
#define FB    33
#define LAMB  0.01f

#define ROWS  (BQ*NFch)      // 512  (b*32+n)
#define KTOT  (SEQ*ECH)      // 65536
#define KSPLIT 32
#define KCHUNK (KTOT/KSPLIT) // 2048
#define BK    32
#define NSTAGE (KCHUNK/BK)   // 64
#define EH    64             // e-channels per k_main CTA (e-split)

// ---------------- scratch (static device globals; no runtime alloc) --------
__device__ float2 g_c[ROWS*WN*TOPM];
__device__ int    g_fidx[ROWS*WN*TOPM];
__device__ float  g_v[6*WN*ECH];
__device__ float  g_xo[(size_t)ROWS*KTOT];          // tf32-rounded, ~134MB
__device__ float  g_Hpart[(size_t)KSPLIT*ROWS*HID];
__device__ float  g_H[ROWS*HID];

#define TWO_PI 6.28318530717958647692f
#define TWO_PI_D 6.28318530717958647692528676655900577

__device__ __forceinline__ int reflect_t(int j) {
    int t = j - 32;
    if (t < 0) t = -t;
    else if (t > SEQ-1) t = 2*(SEQ-1) - t;
    return t;
}

__device__ __forceinline__ uint32_t f2tf32u(float f) {
    uint32_t r; asm("cvt.rna.tf32.f32 %0, %1;" : "=r"(r) : "f"(f)); return r;
}

__device__ __forceinline__ void mma_tf32(float* c, const uint32_t* a, const uint32_t* b) {
    asm volatile("mma.sync.aligned.m16n8k8.row.col.f32.tf32.tf32.f32 "
        "{%0,%1,%2,%3}, {%4,%5,%6,%7}, {%8,%9}, {%0,%1,%2,%3};"
        : "+f"(c[0]), "+f"(c[1]), "+f"(c[2]), "+f"(c[3])
        : "r"(a[0]), "r"(a[1]), "r"(a[2]), "r"(a[3]), "r"(b[0]), "r"(b[1]));
}

__device__ __forceinline__ uint32_t smem_u32(const void* p) {
    uint32_t a;
    asm("{ .reg .u64 t; cvta.to.shared.u64 t, %1; cvt.u32.u64 %0, t; }" : "=r"(a) : "l"(p));
    return a;
}
__device__ __forceinline__ void cp16(uint32_t dst, const void* src) {
    asm volatile("cp.async.ca.shared.global [%0], [%1], 16;" :: "r"(dst), "l"(src));
}

// packed f32x2 helpers (Blackwell FFMA2; IEEE fp32 per lane)
__device__ __forceinline__ void fma2(unsigned long long& acc, unsigned long long a, unsigned long long b) {
    asm("fma.rn.f32x2 %0, %1, %2, %0;" : "+l"(acc) : "l"(a), "l"(b));
}
__device__ __forceinline__ unsigned long long pack2(float lo, float hi) {
    unsigned long long r; asm("mov.b64 %0, {%1, %2};" : "=l"(r) : "f"(lo), "f"(hi)); return r;
}
__device__ __forceinline__ void unpack2(float& lo, float& hi, unsigned long long v) {
    asm("mov.b64 {%0, %1}, %2;" : "=f"(lo), "=f"(hi) : "l"(v));
}

// ---------------- Kernel A: STFT (df64 fp32, exact twiddles) + top-32 ------
__global__ void k_stft(const float* __restrict__ x) {
    __shared__ float s_s[SEQ];
    __shared__ float win_s[NFFT];
    __shared__ float chi_s[NFFT], clo_s[NFFT];
    __shared__ float mhi_s[NFFT], mlo_s[NFFT];
    __shared__ float Sre[WN*FB], Sim[WN*FB], Sab[WN*FB];
    int blk = blockIdx.x;
    int b = blk >> 5, n = blk & 31;
    int tid = threadIdx.x;          // 128

    for (int t = tid; t < SEQ; t += 128) s_s[t] = x[(b*SEQ + t)*NFch + n];
    for (int t = tid; t < NFFT; t += 128) {
        float a = TWO_PI * (float)t / (float)NFFT;
        win_s[t] = 0.5f - 0.5f * (float)cos((double)a);
        double ad = TWO_PI_D * (double)t / 64.0;
        double cd = cos(ad), msd = -sin(ad);
        float ch = (float)cd;  chi_s[t] = ch; clo_s[t] = (float)(cd - (double)ch);
        float mh = (float)msd; mhi_s[t] = mh; mlo_s[t] = (float)(msd - (double)mh);
    }
    __syncthreads();

    for (int task = tid; task < WN*FB; task += 128) {
        int w = task / FB, f = task % FB;
        float rh = 0.f, rl = 0.f, ih = 0.f, il = 0.f;
        for (int k = 0; k < NFFT; k++) {
            float v = s_s[reflect_t(w*HOPL + k)] * win_s[k];
            int a = (f*k) & 63;
            float ch = chi_s[a];
            float ph = v * ch;
            float pe = fmaf(v, ch, -ph);
            pe = fmaf(v, clo_s[a], pe);
            float s  = rh + ph;
            float bb = s - rh;
            float er = (rh - (s - bb)) + (ph - bb);
            rh = s; rl += er + pe;
            float mh = mhi_s[a];
            float qh = v * mh;
            float qe = fmaf(v, mh, -qh);
            qe = fmaf(v, mlo_s[a], qe);
            float s2  = ih + qh;
            float b2  = s2 - ih;
            float e2  = (ih - (s2 - b2)) + (qh - b2);
            ih = s2; il += e2 + qe;
        }
        float rf = rh + rl, imf = ih + il;
        Sre[task] = rf; Sim[task] = imf;
        Sab[task] = (float)sqrt((double)rf*rf + (double)imf*imf);
    }
    __syncthreads();

    if (tid < WN) {
        int w = tid;
        float mag[FB]; bool used[FB];
        for (int f = 0; f < FB; f++) { mag[f] = Sab[w*FB+f]; used[f] = false; }
        int base = (blk*WN + w) * TOPM;
        for (int m = 0; m < TOPM; m++) {
            int best = 0; float bv = -1.f;
            for (int f = 0; f < FB; f++)
                if (!used[f] && mag[f] > bv) { bv = mag[f]; best = f; }
            used[best] = true;
            g_fidx[base+m] = best;
            g_c[base+m] = make_float2(Sre[w*FB+best], Sim[w*FB+best]);
        }
    }
}

// ---------------- Kernel B: v[k][w][f] = sum_e emb[e]*Wk[w,e,f] ------------
__global__ void k_vred(const float* __restrict__ emb,
                       const float* __restrict__ Wr,  const float* __restrict__ Wi,
                       const float* __restrict__ Wrl, const float* __restrict__ Wil,
                       const float* __restrict__ Wrr, const float* __restrict__ Wir) {
    int k = blockIdx.x / WN, w = blockIdx.x % WN;
    const float* Wm = (k==0)?Wr:(k==1)?Wi:(k==2)?Wrl:(k==3)?Wil:(k==4)?Wrr:Wir;
    int f = threadIdx.x;
    const float* base = Wm + (size_t)w*ECH*ECH + f;
    float acc = 0.f;
    #pragma unroll 4
    for (int e = 0; e < ECH; e++) acc = fmaf(emb[e], base[(size_t)e*ECH], acc);
    g_v[(k*WN + w)*ECH + f] = acc;
}

// ---------------- Kernel C: e-split fused Y + parity irfft + OLA + bias ----
// grid = ROWS*2; CTA handles 64 e-channels (half). Compact 64-entry twiddle
// table indexed by (f*t)&63. 43KB smem -> 4 CTAs/SM.
// smem layout (bytes):
//  tw64 ull2[64]     @0     .. 1024
//  y_re float[2048]  @1024  .. 9216
//  y_im float[2048]  @9216  .. 17408
//  ring float[4096]  @17408 .. 33792
//  cc   float2[544]  @33792 .. 38144
//  vs   float[512]   @38144 .. 40192
//  win  float[64]    @40192 .. 40448
//  ienv float[32]    @40448 .. 40576
//  emb  float[64]    @40576 .. 40832
//  fidx int[544]     @40832 .. 43008
#define SMEM_MAIN 43008
__global__ __launch_bounds__(256, 4) void k_main(
        const float* __restrict__ x, const float* __restrict__ emb,
        const float* __restrict__ br, const float* __restrict__ bi) {
    extern __shared__ char smraw[];
    ulonglong2* tw64 = (ulonglong2*)(smraw);
    float*  y_re   = (float*) (smraw + 1024);
    float*  y_im   = (float*) (smraw + 9216);
    float*  ring   = (float*) (smraw + 17408);
    float2* cc     = (float2*)(smraw + 33792);
    float*  vs     = (float*) (smraw + 38144);
    float*  win_s  = (float*) (smraw + 40192);
    float*  ienv   = (float*) (smraw + 40448);
    float*  emb_s  = (float*) (smraw + 40576);
    int*    fidx_s = (int*)   (smraw + 40832);

    int tid = threadIdx.x;          // 256
    int bx  = blockIdx.x;           // (b*32+n)*2 + half
    int blk = bx >> 1, half = bx & 1;
    int e_off = half * EH;
    int b = blk >> 5, n = blk & 31;

    for (int i = tid; i < 64; i += 256) {
        double ad = TWO_PI_D * (double)i / 64.0;
        float c = (float)cos(ad), s = (float)sin(ad);
        ulonglong2 v; v.x = pack2(c, c); v.y = pack2(-s, -s);
        tw64[i] = v;
    }
    for (int i = tid; i < NFFT; i += 256) {
        float a = TWO_PI * (float)i / (float)NFFT;
        win_s[i] = 0.5f - 0.5f * (float)cos((double)a);
    }
    for (int i = tid; i < HOPL; i += 256) {
        float a = TWO_PI * (float)i / (float)NFFT;
        float c = (float)cos((double)a);
        float w0 = 0.5f - 0.5f*c, w1 = 0.5f + 0.5f*c;
        ienv[i] = 1.0f / (w0*w0 + w1*w1);
    }
    for (int i = tid; i < EH; i += 256) emb_s[i] = emb[e_off + i];
    for (int i = tid; i < WN*TOPM; i += 256) {
        cc[i]     = g_c[blk*WN*TOPM + i];
        fidx_s[i] = g_fidx[blk*WN*TOPM + i];
    }
    __syncthreads();

    int lane = tid & 31, wid = tid >> 5;
    int e0l = (lane & 15) << 2;                 // local e 0..60 (quad)
    int t0  = wid*4 + ((lane >> 4) << 1);       // base t 0..30 (pair)

    for (int w = 0; w < WN; w++) {
        for (int i = tid; i < 8*EH; i += 256) {
            int k = i >> 6, e = i & 63;
            float v;
            if (k < 6)      v = g_v[(k*WN + w)*ECH + e_off + e];
            else if (k == 6) v = br[w*ECH + e_off + e];
            else             v = bi[w*ECH + e_off + e];
            vs[i] = v;
        }
        __syncthreads();

        // Y compute for this e-half, indexed by rank m (scale folded)
        for (int i = tid; i < EH*TOPM; i += 256) {
            int m = i >> 6, e = i & 63;
            float2 c0 = cc[w*TOPM + m];
            float2 cl = (w > 0)    ? cc[(w-1)*TOPM + m] : make_float2(0.f,0.f);
            float2 cr = (w < WN-1) ? cc[(w+1)*TOPM + m] : make_float2(0.f,0.f);
            float vr  = vs[e],       vi  = vs[EH+e];
            float vrl = vs[2*EH+e],  vil = vs[3*EH+e];
            float vrr = vs[4*EH+e],  vir = vs[5*EH+e];
            float ore = c0.x*vr - c0.y*vi + cl.x*vrl - cl.y*vil + cr.x*vrr - cr.y*vir + vs[6*EH+e];
            float oim = c0.y*vr + c0.x*vi + cl.y*vrl + cl.x*vil + cr.y*vrr + cr.x*vir + vs[7*EH+e];
            float yre = fmaxf(fmaxf(ore, 0.f) - LAMB, 0.f);
            float yim = fmaxf(fmaxf(oim, 0.f) - LAMB, 0.f);
            int f = fidx_s[w*TOPM + m];
            if (f == 0 || f == FB-1) {
                y_re[i] = yre * 0.015625f;   // 1/64, imag ignored by irfft
                y_im[i] = 0.f;
            } else {
                y_re[i] = yre * 0.03125f;    // 2/64
                y_im[i] = yim * 0.03125f;
            }
        }
        __syncthreads();

        // irfft over 32 top-k bins, parity-split accumulators, compact table
        unsigned long long aE[2][2], aO[2][2];   // [kk][e-pair]
        #pragma unroll
        for (int kk = 0; kk < 2; kk++) {
            aE[kk][0] = aE[kk][1] = 0ull;
            aO[kk][0] = aO[kk][1] = 0ull;
        }

        #pragma unroll 4
        for (int m = 0; m < TOPM; m++) {
            int f = fidx_s[w*TOPM + m];                  // warp-uniform
            ulonglong2 yr = *(const ulonglong2*)&y_re[m*EH + e0l];
            ulonglong2 yi = *(const ulonglong2*)&y_im[m*EH + e0l];
            int ft = f * t0;
            ulonglong2 cs0 = tw64[ft & 63];
            ulonglong2 cs1 = tw64[(ft + f) & 63];
            if (f & 1) {
                fma2(aO[0][0], yr.x, cs0.x); fma2(aO[0][0], yi.x, cs0.y);
                fma2(aO[0][1], yr.y, cs0.x); fma2(aO[0][1], yi.y, cs0.y);
                fma2(aO[1][0], yr.x, cs1.x); fma2(aO[1][0], yi.x, cs1.y);
                fma2(aO[1][1], yr.y, cs1.x); fma2(aO[1][1], yi.y, cs1.y);
            } else {
                fma2(aE[0][0], yr.x, cs0.x); fma2(aE[0][0], yi.x, cs0.y);
                fma2(aE[0][1], yr.y, cs0.x); fma2(aE[0][1], yi.y, cs0.y);
                fma2(aE[1][0], yr.x, cs1.x); fma2(aE[1][0], yi.x, cs1.y);
                fma2(aE[1][1], yr.y, cs1.x); fma2(aE[1][1], yi.y, cs1.y);
            }
        }

        // combine parities: out(t)=Pe+Po, out(t+32)=Pe-Po; window + ring OLA
        #pragma unroll
        for (int kk = 0; kk < 2; kk++) {
            int t  = t0 + kk;            // 0..31 : accumulates onto prev window
            int tm = t + 32;             // 32..63: fresh overwrite
            float pe0, pe1, pe2, pe3, po0, po1, po2, po3;
            unpack2(pe0, pe1, aE[kk][0]); unpack2(pe2, pe3, aE[kk][1]);
            unpack2(po0, po1, aO[kk][0]); unpack2(po2, po3, aO[kk][1]);

            float wt = win_s[t], wmr = win_s[tm];
            int slot_t = (w*HOPL + t)  & 63;
            int slot_m = (w*HOPL + tm) & 63;

            float4 vt, vm;
            vt.x = (pe0+po0)*wt;  vt.y = (pe1+po1)*wt;
            vt.z = (pe2+po2)*wt;  vt.w = (pe3+po3)*wt;
            vm.x = (pe0-po0)*wmr; vm.y = (pe1-po1)*wmr;
            vm.z = (pe2-po2)*wmr; vm.w = (pe3-po3)*wmr;

            float4* rpt = (float4*)&ring[slot_t*EH + e0l];
            if (w > 0) {
                float4 o = *rpt;
                vt.x += o.x; vt.y += o.y; vt.z += o.z; vt.w += o.w;
            }
            *rpt = vt;
            *(float4*)&ring[slot_m*EH + e0l] = vm;
        }
        __syncthreads();

        if (w > 0) {
            for (int i = tid; i < HOPL*EH; i += 256) {
                int r = i >> 6, e = i & 63;
                int t_out = (w-1)*HOPL + r;
                int slot = (w*HOPL + r) & 63;
                float val = ring[slot*EH + e] * ienv[r]
                          + x[(b*SEQ + t_out)*NFch + n] * emb_s[e];
                g_xo[(size_t)blk*KTOT + t_out*ECH + e_off + e] = __uint_as_float(f2tf32u(val));
            }
        }
        __syncthreads();
    }
}

// ---------------- Kernel D: FC1 split-K, 1xTF32 tensor-core GEMM -----------
#define SA 36
#define SB 136
#define STAGE_A (128*SA)
#define STAGE_B (BK*SB)
#define STAGE_F (STAGE_A + STAGE_B)
#define SMEM_FC1 (2*STAGE_F*4)      // 71680 B
__global__ __launch_bounds__(256, 2) void k_fc1(const float* __restrict__ w1) {
    extern __shared__ float sm[];

    int m0 = blockIdx.x * 128, n0 = blockIdx.y * 128;
    int kbase = blockIdx.z * KCHUNK;
    int tid = threadIdx.x, lane = tid & 31, wid = tid >> 5;
    int wm = wid >> 1, wn = wid & 1;
    int ra = lane >> 2, ca = lane & 3;

    float acc[2][8][4];
    #pragma unroll
    for (int i = 0; i < 2; i++)
        #pragma unroll
        for (int j = 0; j < 8; j++)
            #pragma unroll
            for (int q = 0; q < 4; q++) acc[i][j][q] = 0.f;

    int am[4], ak[4], bk[4], bn[4];
    #pragma unroll
    for (int i = 0; i < 4; i++) {
        int c = tid + i*256;
        am[i] = c >> 3;  ak[i] = (c & 7) * 4;
        bk[i] = c >> 5;  bn[i] = (c & 31) * 4;
    }

    uint32_t smA[2], smB[2];
    smA[0] = smem_u32(sm);
    smB[0] = smA[0] + STAGE_A*4;
    smA[1] = smA[0] + STAGE_F*4;
    smB[1] = smB[0] + STAGE_F*4;

    {
        int kc = kbase;
        #pragma unroll
        for (int i = 0; i < 4; i++) {
            cp16(smA[0] + (am[i]*SA + ak[i])*4, &g_xo[(size_t)(m0+am[i])*KTOT + kc + ak[i]]);
            cp16(smB[0] + (bk[i]*SB + bn[i])*4, &w1[(size_t)(kc+bk[i])*HID + n0 + bn[i]]);
        }
        asm volatile("cp.async.commit_group;");
    }

    for (int it = 0; it < NSTAGE; it++) {
        if (it + 1 < NSTAGE) {
            int buf = (it+1) & 1;
            int kc = kbase + (it+1)*BK;
            #pragma unroll
            for (int i = 0; i < 4; i++) {
                cp16(smA[buf] + (am[i]*SA + ak[i])*4, &g_xo[(size_t)(m0+am[i])*KTOT + kc + ak[i]]);
                cp16(smB[buf] + (bk[i]*SB + bn[i])*4, &w1[(size_t)(kc+bk[i])*HID + n0 + bn[i]]);
            }
            asm volatile("cp.async.commit_group;");
            asm volatile("cp.async.wait_group 1;");
        } else {
            asm volatile("cp.async.wait_group 0;");
        }
        __syncthreads();

        const float* As = sm + (it & 1) * STAGE_F;
        const float* Bs = As + STAGE_A;

        #pragma unroll
        for (int ks = 0; ks < BK/8; ks++) {
            int k0 = ks*8 + ca;
            uint32_t ah[2][4];
            #pragma unroll
            for (int i = 0; i < 2; i++) {
                int mb = wm*32 + i*16;
                ah[i][0] = __float_as_uint(As[(mb+ra  )*SA + k0  ]);
                ah[i][1] = __float_as_uint(As[(mb+ra+8)*SA + k0  ]);
                ah[i][2] = __float_as_uint(As[(mb+ra  )*SA + k0+4]);
                ah[i][3] = __float_as_uint(As[(mb+ra+8)*SA + k0+4]);
            }
            #pragma unroll
            for (int j = 0; j < 8; j++) {
                int nb = wn*64 + j*8 + ra;
                uint32_t bh[2];
                bh[0] = f2tf32u(Bs[(k0  )*SB + nb]);
                bh[1] = f2tf32u(Bs[(k0+4)*SB + nb]);
                #pragma unroll
                for (int i = 0; i < 2; i++)
                    mma_tf32(acc[i][j], ah[i], bh);
            }
        }
        __syncthreads();
    }

    size_t base = (size_t)blockIdx.z * (ROWS*HID);
    #pragma unroll
    for (int i = 0; i < 2; i++) {
        #pragma unroll
        for (int j = 0; j < 8; j++) {
            int row = m0 + wm*32 + i*16 + ra;
            int col = n0 + wn*64 + j*8 + ca*2;
            *(float2*)&g_Hpart[base + (size_t)row*HID + col]     = make_float2(acc[i][j][0], acc[i][j][1]);
            *(float2*)&g_Hpart[base + (size_t)(row+8)*HID + col] = make_float2(acc[i][j][2], acc[i][j][3]);
        }
    }
}

__global__ void k_hred() {
    int i = blockIdx.x * 256 + threadIdx.x;
    if (i >= ROWS*HID) return;
    float s = 0.f;
    #pragma unroll
    for (int z = 0; z < KSPLIT; z++) s += g_Hpart[(size_t)z*(ROWS*HID) + i];
    g_H[i] = s;
}

// ---------------- Kernel E: leaky_relu + FC2 (exact fp32) + transpose ------
__global__ void k_fc2(const float* __restrict__ b1, const float* __restrict__ w2,
                      const float* __restrict__ b2, float* __restrict__ out) {
    __shared__ float hrow[HID];
    int row = blockIdx.x;
    int tid = threadIdx.x;          // 96
    for (int i = tid; i < HID; i += PRED) {
        float v = g_H[row*HID + i] + b1[i];
        hrow[i] = v > 0.f ? v : 0.01f * v;
    }
    __syncthreads();
    int b = row >> 5, n = row & 31;
    float acc = b2[tid];
    #pragma unroll 4
    for (int h = 0; h < HID; h++) acc = fmaf(hrow[h], w2[h*PRED + tid], acc);
    out[(b*PRED + tid)*NFch + n] = acc;
}

// ---------------------------------------------------------------------------
extern "C" void kernel_launch(void* const* d_in, const int* in_sizes, int n_in,
                              void* d_out, int out_size) {
    const float* x   = (const float*)d_in[0];
    const float* emb = (const float*)d_in[1];
    const float* br  = (const float*)d_in[8];
    const float* bi  = (const float*)d_in[9];
    const float* w1  = (const float*)d_in[10];
    const float* b1  = (const float*)d_in[11];
    const float* w2  = (const float*)d_in[12];
    const float* b2  = (const float*)d_in[13];
    float* out = (float*)d_out;

    cudaFuncSetAttribute(k_main, cudaFuncAttributeMaxDynamicSharedMemorySize, SMEM_MAIN);
    cudaFuncSetAttribute(k_fc1,  cudaFuncAttributeMaxDynamicSharedMemorySize, SMEM_FC1);

    k_stft<<<ROWS, 128>>>(x);
    k_vred<<<6*WN, 128>>>(emb, (const float*)d_in[2], (const float*)d_in[3],
                          (const float*)d_in[4], (const float*)d_in[5],
                          (const float*)d_in[6], (const float*)d_in[7]);
    k_main<<<ROWS*2, 256, SMEM_MAIN>>>(x, emb, br, bi);
    k_fc1<<<dim3(4, 4, KSPLIT), 256, SMEM_FC1>>>(w1);
    k_hred<<<(ROWS*HID + 255)/256, 256>>>();
    k_fc2<<<ROWS, PRED>>>(b1, w2, b2, out);
}